// round 2
// baseline (speedup 1.0000x reference)
#include <cuda_runtime.h>
#include <math.h>

#define S_LEN 2048
#define HID_  2048
#define NH    32
#define NKV   8
#define HD    64
#define LAMBDA_INIT 0.7836057665316245f  // 0.8 - 0.6*exp(-0.3*12)

// ---------------- scratch (device globals; no allocation allowed) ----------------
__device__ float g_q[(size_t)S_LEN * 4096];   // [S, 2*HID]  (q1 | q2)
__device__ float g_k[(size_t)S_LEN * 1024];   // [S, 2*D*HKV] (k1 | k2)
__device__ float g_v[(size_t)S_LEN * 512];    // [S, D*HKV]
__device__ float g_att[(size_t)S_LEN * HID_]; // [S, H*D]  pre-Wo
__device__ float g_lambda;

// ---------------- generic SGEMM:  C[M,N] = A[M,K] @ B[N,K]^T ----------------
// 64x64 block tile, 16 k-slice, 256 threads, 4x4 micro-tile, float4 smem reads.
__global__ void __launch_bounds__(256) sgemm_nt(const float* __restrict__ A,
                                               const float* __restrict__ B,
                                               float* __restrict__ C,
                                               int M, int N, int K) {
    __shared__ float As[16][68];
    __shared__ float Bs[16][68];
    const int tid = threadIdx.x;
    const int tx = tid & 15, ty = tid >> 4;
    const int m0 = blockIdx.y << 6, n0 = blockIdx.x << 6;
    const int lr = tid >> 2;          // 0..63 : row within tile
    const int lk = (tid & 3) << 2;    // 0,4,8,12 : k offset (float4)
    const float* Ap = A + (size_t)(m0 + lr) * K + lk;
    const float* Bp = B + (size_t)(n0 + lr) * K + lk;

    float acc[4][4] = {};
    for (int k0 = 0; k0 < K; k0 += 16) {
        float4 a4 = *(const float4*)(Ap + k0);
        float4 b4 = *(const float4*)(Bp + k0);
        __syncthreads();
        As[lk + 0][lr] = a4.x; As[lk + 1][lr] = a4.y;
        As[lk + 2][lr] = a4.z; As[lk + 3][lr] = a4.w;
        Bs[lk + 0][lr] = b4.x; Bs[lk + 1][lr] = b4.y;
        Bs[lk + 2][lr] = b4.z; Bs[lk + 3][lr] = b4.w;
        __syncthreads();
#pragma unroll
        for (int kk = 0; kk < 16; kk++) {
            float4 av = *(const float4*)&As[kk][ty << 2];
            float4 bv = *(const float4*)&Bs[kk][tx << 2];
            float a[4] = {av.x, av.y, av.z, av.w};
            float b[4] = {bv.x, bv.y, bv.z, bv.w};
#pragma unroll
            for (int i = 0; i < 4; i++)
#pragma unroll
                for (int j = 0; j < 4; j++) acc[i][j] = fmaf(a[i], b[j], acc[i][j]);
        }
    }
#pragma unroll
    for (int i = 0; i < 4; i++) {
        float4 r = {acc[i][0], acc[i][1], acc[i][2], acc[i][3]};
        *(float4*)(C + (size_t)(m0 + (ty << 2) + i) * N + n0 + (tx << 2)) = r;
    }
}

// ---------------- RoPE (in-place on q or k buffer) ----------------
// One thread per (s, slot, d-half). slot = 64-wide head slot. rowstride in floats.
// position_ids is deterministically arange(B*S) % S == s for B=1, so we compute
// the position directly (avoids the int64-vs-int32 dtype trap in the input).
__global__ void rope_kernel(float* __restrict__ x,
                            int nslots, int rowstride, int total) {
    int idx = blockIdx.x * blockDim.x + threadIdx.x;
    if (idx >= total) return;
    int dh = idx & 31;
    int slot = (idx >> 5) % nslots;
    int s = idx / (nslots << 5);
    float pos = (float)s;
    // inv_freq = 10000^(-2*dh/64)
    float invf = expf(-(2.0f * dh / 64.0f) * 9.210340371976184f);
    float ang = pos * invf;
    float c = cosf(ang), sn = sinf(ang);
    float* row = x + (size_t)s * rowstride + slot * 64;
    float x0 = row[dh], x1 = row[dh + 32];
    row[dh]      = x0 * c - x1 * sn;
    row[dh + 32] = x1 * c + x0 * sn;
}

// ---------------- lambda_full ----------------
__global__ void lambda_kernel(const float* lq1, const float* lk1,
                              const float* lq2, const float* lk2) {
    float s1 = 0.f, s2 = 0.f;
    for (int i = threadIdx.x; i < 64; i += 32) {
        s1 += lq1[i] * lk1[i];
        s2 += lq2[i] * lk2[i];
    }
#pragma unroll
    for (int o = 16; o; o >>= 1) {
        s1 += __shfl_xor_sync(0xffffffffu, s1, o);
        s2 += __shfl_xor_sync(0xffffffffu, s2, o);
    }
    if (threadIdx.x == 0) g_lambda = expf(s1) - expf(s2) + LAMBDA_INIT;
}

// ---------------- fused dual flash attention + diff + RMSNorm ----------------
// grid (qb=32, h=32), 256 threads. BM=BN=64. Row r = ty+16*i, col c = tx+16*j.
// smem: Q1,Q2 (persistent), K1(->P1), K2(->P2), V — each 64x65 floats.
#define ATT_PAD 65
#define ATT_SMEM (5 * 64 * ATT_PAD * 4)

__global__ void __launch_bounds__(256) diff_attn_kernel(const float* __restrict__ subln_w) {
    extern __shared__ float sm[];
    float* sQ1 = sm;
    float* sQ2 = sQ1 + 64 * ATT_PAD;
    float* sK1 = sQ2 + 64 * ATT_PAD;  // reused as sP1
    float* sK2 = sK1 + 64 * ATT_PAD;  // reused as sP2
    float* sV  = sK2 + 64 * ATT_PAD;

    const int qb = blockIdx.x, h = blockIdx.y;
    const int hk = h >> 2;  // NREP = 4
    const int tid = threadIdx.x;
    const int ty = tid >> 4, tx = tid & 15;

    // load Q tiles (q1 at col h*64, q2 at col 2048 + h*64)
    for (int idx = tid * 4; idx < 64 * 64; idx += 1024) {
        int r = idx >> 6, d = idx & 63;
        const float* qrow = g_q + (size_t)(qb * 64 + r) * 4096 + h * 64 + d;
        float4 q1 = *(const float4*)qrow;
        float4 q2 = *(const float4*)(qrow + 2048);
        float* p1 = &sQ1[r * ATT_PAD + d];
        float* p2 = &sQ2[r * ATT_PAD + d];
        p1[0] = q1.x; p1[1] = q1.y; p1[2] = q1.z; p1[3] = q1.w;
        p2[0] = q2.x; p2[1] = q2.y; p2[2] = q2.z; p2[3] = q2.w;
    }

    float O1[4][4] = {}, O2[4][4] = {};
    float m1[4], l1[4], m2[4], l2[4];
#pragma unroll
    for (int i = 0; i < 4; i++) { m1[i] = m2[i] = -1e30f; l1[i] = l2[i] = 0.f; }

    for (int kb = 0; kb <= qb; kb++) {
        __syncthreads();  // previous iteration's P fully consumed
        // load K1, K2, V tiles
        for (int idx = tid * 4; idx < 64 * 64; idx += 1024) {
            int c = idx >> 6, d = idx & 63;
            const float* krow = g_k + (size_t)(kb * 64 + c) * 1024 + hk * 64 + d;
            float4 k1 = *(const float4*)krow;
            float4 k2 = *(const float4*)(krow + 512);
            const float* vrow = g_v + (size_t)(kb * 64 + c) * 512 + hk * 64 + d;
            float4 vv = *(const float4*)vrow;
            float* p1 = &sK1[c * ATT_PAD + d];
            float* p2 = &sK2[c * ATT_PAD + d];
            float* pv = &sV[c * ATT_PAD + d];
            p1[0] = k1.x; p1[1] = k1.y; p1[2] = k1.z; p1[3] = k1.w;
            p2[0] = k2.x; p2[1] = k2.y; p2[2] = k2.z; p2[3] = k2.w;
            pv[0] = vv.x; pv[1] = vv.y; pv[2] = vv.z; pv[3] = vv.w;
        }
        __syncthreads();

        // scores
        float s1[4][4] = {}, s2[4][4] = {};
#pragma unroll 4
        for (int d = 0; d < 64; d++) {
            float a1[4], b1[4], a2[4], b2[4];
#pragma unroll
            for (int i = 0; i < 4; i++) {
                a1[i] = sQ1[(ty + 16 * i) * ATT_PAD + d];
                a2[i] = sQ2[(ty + 16 * i) * ATT_PAD + d];
            }
#pragma unroll
            for (int j = 0; j < 4; j++) {
                b1[j] = sK1[(tx + 16 * j) * ATT_PAD + d];
                b2[j] = sK2[(tx + 16 * j) * ATT_PAD + d];
            }
#pragma unroll
            for (int i = 0; i < 4; i++)
#pragma unroll
                for (int j = 0; j < 4; j++) {
                    s1[i][j] = fmaf(a1[i], b1[j], s1[i][j]);
                    s2[i][j] = fmaf(a2[i], b2[j], s2[i][j]);
                }
        }
        const float scale = 0.125f;  // 1/sqrt(64)
#pragma unroll
        for (int i = 0; i < 4; i++)
#pragma unroll
            for (int j = 0; j < 4; j++) { s1[i][j] *= scale; s2[i][j] *= scale; }
        if (kb == qb) {
#pragma unroll
            for (int i = 0; i < 4; i++) {
                int qg = qb * 64 + ty + 16 * i;
#pragma unroll
                for (int j = 0; j < 4; j++) {
                    int kg = kb * 64 + tx + 16 * j;
                    if (kg > qg) { s1[i][j] = -1e30f; s2[i][j] = -1e30f; }
                }
            }
        }

        // online softmax, both streams
#pragma unroll
        for (int i = 0; i < 4; i++) {
            // stream 1
            float mx = fmaxf(fmaxf(s1[i][0], s1[i][1]), fmaxf(s1[i][2], s1[i][3]));
#pragma unroll
            for (int o = 8; o; o >>= 1) mx = fmaxf(mx, __shfl_xor_sync(0xffffffffu, mx, o, 16));
            float mn = fmaxf(m1[i], mx);
            float corr = expf(m1[i] - mn);
            float rs = 0.f;
#pragma unroll
            for (int j = 0; j < 4; j++) { float p = expf(s1[i][j] - mn); s1[i][j] = p; rs += p; }
#pragma unroll
            for (int o = 8; o; o >>= 1) rs += __shfl_xor_sync(0xffffffffu, rs, o, 16);
            l1[i] = l1[i] * corr + rs;
            m1[i] = mn;
#pragma unroll
            for (int j = 0; j < 4; j++) O1[i][j] *= corr;
            // stream 2
            mx = fmaxf(fmaxf(s2[i][0], s2[i][1]), fmaxf(s2[i][2], s2[i][3]));
#pragma unroll
            for (int o = 8; o; o >>= 1) mx = fmaxf(mx, __shfl_xor_sync(0xffffffffu, mx, o, 16));
            mn = fmaxf(m2[i], mx);
            corr = expf(m2[i] - mn);
            rs = 0.f;
#pragma unroll
            for (int j = 0; j < 4; j++) { float p = expf(s2[i][j] - mn); s2[i][j] = p; rs += p; }
#pragma unroll
            for (int o = 8; o; o >>= 1) rs += __shfl_xor_sync(0xffffffffu, rs, o, 16);
            l2[i] = l2[i] * corr + rs;
            m2[i] = mn;
#pragma unroll
            for (int j = 0; j < 4; j++) O2[i][j] *= corr;
        }

        __syncthreads();  // all K reads complete before P overwrites the buffers
#pragma unroll
        for (int i = 0; i < 4; i++)
#pragma unroll
            for (int j = 0; j < 4; j++) {
                sK1[(ty + 16 * i) * ATT_PAD + tx + 16 * j] = s1[i][j];
                sK2[(ty + 16 * i) * ATT_PAD + tx + 16 * j] = s2[i][j];
            }
        __syncthreads();

        // O += P @ V
#pragma unroll 2
        for (int c = 0; c < 64; c++) {
            float v[4];
#pragma unroll
            for (int j = 0; j < 4; j++) v[j] = sV[c * ATT_PAD + tx + 16 * j];
#pragma unroll
            for (int i = 0; i < 4; i++) {
                float p1 = sK1[(ty + 16 * i) * ATT_PAD + c];
                float p2 = sK2[(ty + 16 * i) * ATT_PAD + c];
#pragma unroll
                for (int j = 0; j < 4; j++) {
                    O1[i][j] = fmaf(p1, v[j], O1[i][j]);
                    O2[i][j] = fmaf(p2, v[j], O2[i][j]);
                }
            }
        }
    }

    // epilogue: diff, RMSNorm over D, subln scale, (1 - lambda_init)
    const float lam = g_lambda;
    float w[4];
#pragma unroll
    for (int j = 0; j < 4; j++) w[j] = subln_w[tx + 16 * j];
#pragma unroll
    for (int i = 0; i < 4; i++) {
        float inv1 = 1.f / l1[i], inv2 = 1.f / l2[i];
        float o[4];
        float ss = 0.f;
#pragma unroll
        for (int j = 0; j < 4; j++) {
            o[j] = O1[i][j] * inv1 - lam * (O2[i][j] * inv2);
            ss += o[j] * o[j];
        }
#pragma unroll
        for (int off = 8; off; off >>= 1) ss += __shfl_xor_sync(0xffffffffu, ss, off, 16);
        float rms = rsqrtf(ss * (1.0f / 64.0f) + 1e-6f);
        float k = rms * (1.0f - LAMBDA_INIT);
        int sg = qb * 64 + ty + 16 * i;
#pragma unroll
        for (int j = 0; j < 4; j++)
            g_att[(size_t)sg * HID_ + h * 64 + tx + 16 * j] = o[j] * k * w[j];
    }
}

// ---------------- launch ----------------
extern "C" void kernel_launch(void* const* d_in, const int* in_sizes, int n_in,
                              void* d_out, int out_size) {
    const float* hs   = (const float*)d_in[0];
    const float* Wq   = (const float*)d_in[1];
    const float* Wk   = (const float*)d_in[2];
    const float* Wv   = (const float*)d_in[3];
    const float* Wo   = (const float*)d_in[4];
    const float* lq1  = (const float*)d_in[5];
    const float* lk1  = (const float*)d_in[6];
    const float* lq2  = (const float*)d_in[7];
    const float* lk2  = (const float*)d_in[8];
    const float* subw = (const float*)d_in[9];
    float* out = (float*)d_out;

    void *pq, *pk, *pv, *pa;
    cudaGetSymbolAddress(&pq, g_q);
    cudaGetSymbolAddress(&pk, g_k);
    cudaGetSymbolAddress(&pv, g_v);
    cudaGetSymbolAddress(&pa, g_att);
    cudaFuncSetAttribute(diff_attn_kernel,
                         cudaFuncAttributeMaxDynamicSharedMemorySize, ATT_SMEM);

    // projections
    sgemm_nt<<<dim3(4096 / 64, S_LEN / 64), 256>>>(hs, Wq, (float*)pq, S_LEN, 4096, HID_);
    sgemm_nt<<<dim3(1024 / 64, S_LEN / 64), 256>>>(hs, Wk, (float*)pk, S_LEN, 1024, HID_);
    sgemm_nt<<<dim3(512 / 64,  S_LEN / 64), 256>>>(hs, Wv, (float*)pv, S_LEN, 512, HID_);

    // rope: q has 64 head-slots (q1|q2), k has 16 (k1|k2)
    {
        int tq = S_LEN * 64 * 32;
        rope_kernel<<<(tq + 255) / 256, 256>>>((float*)pq, 64, 4096, tq);
        int tk = S_LEN * 16 * 32;
        rope_kernel<<<(tk + 255) / 256, 256>>>((float*)pk, 16, 1024, tk);
    }

    lambda_kernel<<<1, 32>>>(lq1, lk1, lq2, lk2);

    diff_attn_kernel<<<dim3(S_LEN / 64, NH), 256, ATT_SMEM>>>(subw);

    // output projection
    sgemm_nt<<<dim3(HID_ / 64, S_LEN / 64), 256>>>((float*)pa, Wo, out, S_LEN, HID_, HID_);
}

// round 4
// speedup vs baseline: 1.3406x; 1.3406x over previous
#include <cuda_runtime.h>
#include <cuda_bf16.h>
#include <cstdint>
#include <math.h>

typedef unsigned int u32;

#define S_LEN 2048
#define HID_  2048
#define NH    32
#define NKV   8
#define HD    64
#define LAMBDA_INIT 0.7836057665316245f  // 0.8 - 0.6*exp(-0.3*12)

// ---------------- scratch (device globals; no allocation allowed) ----------------
__device__ float g_q[(size_t)S_LEN * 4096];   // [S, 2*HID]  (q1 | q2)
__device__ float g_k[(size_t)S_LEN * 1024];   // [S, 2*D*HKV] (k1 | k2)
__device__ float g_v[(size_t)S_LEN * 512];    // [S, D*HKV]
__device__ float g_att[(size_t)S_LEN * HID_]; // [S, H*D]  pre-Wo
__device__ float g_lambda;

// ================= bf16 split-precision tensor-core GEMM =================
// C[M,N] = A[M,K] @ B[N,K]^T, fp32 in/out, ~fp32 accuracy via 2-term bf16
// split (x = hi + lo) and 3 MMA passes (hh, hl, lh). M,N mult of 128, K of 32.
// Block 128x128, 256 thr = 8 warps (2x4), warp tile 64x32, BK=32.

__device__ __forceinline__ u32 pack_bf(float x) {
    float hf = __bfloat162float(__float2bfloat16(x));
    u32 hi, lo;
    {
        __nv_bfloat16 h = __float2bfloat16(x);
        __nv_bfloat16 l = __float2bfloat16(x - hf);
        unsigned short hs = *reinterpret_cast<unsigned short*>(&h);
        unsigned short ls = *reinterpret_cast<unsigned short*>(&l);
        hi = (u32)hs; lo = (u32)ls;
    }
    return (hi << 16) | lo;
}

__device__ __forceinline__ void mma_bf16(float* c, const u32* a, const u32* b) {
    asm volatile(
        "mma.sync.aligned.m16n8k16.row.col.f32.bf16.bf16.f32 "
        "{%0,%1,%2,%3}, {%4,%5,%6,%7}, {%8,%9}, {%0,%1,%2,%3};"
        : "+f"(c[0]), "+f"(c[1]), "+f"(c[2]), "+f"(c[3])
        : "r"(a[0]), "r"(a[1]), "r"(a[2]), "r"(a[3]), "r"(b[0]), "r"(b[1]));
}

#define GSTR 36  // padded u32 words per smem row (BK=32 + 4)

__global__ void __launch_bounds__(256) gemm_bf3(const float* __restrict__ A,
                                               const float* __restrict__ B,
                                               float* __restrict__ C,
                                               int M, int N, int K) {
    __shared__ u32 sA[128 * GSTR];
    __shared__ u32 sB[128 * GSTR];

    const int tid  = threadIdx.x;
    const int lane = tid & 31;
    const int warp = tid >> 5;
    const int wm = (warp >> 2) * 64;   // warp m-offset in tile
    const int wn = (warp & 3) * 32;    // warp n-offset in tile
    const int m0 = blockIdx.y * 128;
    const int n0 = blockIdx.x * 128;
    const int q  = lane & 3;           // thread-in-group
    const int g  = lane >> 2;          // group id (0..7)

    float acc[4][4][4] = {};           // [mi][nj][frag]

    // prefetch registers: 4 float4 for A, 4 for B per tile
    float4 pa[4], pb[4];
    int rowA[4], slA[4];
#pragma unroll
    for (int it = 0; it < 4; it++) {
        int idx = tid + it * 256;      // 0..1023 over 128 rows x 8 float4-slots
        rowA[it] = idx >> 3; slA[it] = idx & 7;
    }

    // load first tile
#pragma unroll
    for (int it = 0; it < 4; it++) {
        pa[it] = *(const float4*)(A + (size_t)(m0 + rowA[it]) * K + slA[it] * 4);
        pb[it] = *(const float4*)(B + (size_t)(n0 + rowA[it]) * K + slA[it] * 4);
    }

    for (int k0 = 0; k0 < K; k0 += 32) {
        // store prefetched tile into smem (packed hi|lo)
#pragma unroll
        for (int it = 0; it < 4; it++) {
            uint4 wa, wb;
            wa.x = pack_bf(pa[it].x); wa.y = pack_bf(pa[it].y);
            wa.z = pack_bf(pa[it].z); wa.w = pack_bf(pa[it].w);
            wb.x = pack_bf(pb[it].x); wb.y = pack_bf(pb[it].y);
            wb.z = pack_bf(pb[it].z); wb.w = pack_bf(pb[it].w);
            *(uint4*)&sA[rowA[it] * GSTR + slA[it] * 4] = wa;
            *(uint4*)&sB[rowA[it] * GSTR + slA[it] * 4] = wb;
        }
        __syncthreads();

        // prefetch next tile
        if (k0 + 32 < K) {
#pragma unroll
            for (int it = 0; it < 4; it++) {
                pa[it] = *(const float4*)(A + (size_t)(m0 + rowA[it]) * K + k0 + 32 + slA[it] * 4);
                pb[it] = *(const float4*)(B + (size_t)(n0 + rowA[it]) * K + k0 + 32 + slA[it] * 4);
            }
        }

        // compute: 2 k16 steps
#pragma unroll
        for (int kk = 0; kk < 32; kk += 16) {
            u32 ah[4][4], al[4][4], bh[4][2], bl[4][2];
#pragma unroll
            for (int mi = 0; mi < 4; mi++) {
                int r = wm + mi * 16 + g;
                uint2 w0 = *(uint2*)&sA[r * GSTR + kk + 2 * q];
                uint2 w1 = *(uint2*)&sA[(r + 8) * GSTR + kk + 2 * q];
                uint2 w2 = *(uint2*)&sA[r * GSTR + kk + 8 + 2 * q];
                uint2 w3 = *(uint2*)&sA[(r + 8) * GSTR + kk + 8 + 2 * q];
                ah[mi][0] = __byte_perm(w0.x, w0.y, 0x7632); al[mi][0] = __byte_perm(w0.x, w0.y, 0x5410);
                ah[mi][1] = __byte_perm(w1.x, w1.y, 0x7632); al[mi][1] = __byte_perm(w1.x, w1.y, 0x5410);
                ah[mi][2] = __byte_perm(w2.x, w2.y, 0x7632); al[mi][2] = __byte_perm(w2.x, w2.y, 0x5410);
                ah[mi][3] = __byte_perm(w3.x, w3.y, 0x7632); al[mi][3] = __byte_perm(w3.x, w3.y, 0x5410);
            }
#pragma unroll
            for (int nj = 0; nj < 4; nj++) {
                int n = wn + nj * 8 + g;
                uint2 w0 = *(uint2*)&sB[n * GSTR + kk + 2 * q];
                uint2 w1 = *(uint2*)&sB[n * GSTR + kk + 8 + 2 * q];
                bh[nj][0] = __byte_perm(w0.x, w0.y, 0x7632); bl[nj][0] = __byte_perm(w0.x, w0.y, 0x5410);
                bh[nj][1] = __byte_perm(w1.x, w1.y, 0x7632); bl[nj][1] = __byte_perm(w1.x, w1.y, 0x5410);
            }
#pragma unroll
            for (int mi = 0; mi < 4; mi++)
#pragma unroll
                for (int nj = 0; nj < 4; nj++) {
                    mma_bf16(acc[mi][nj], ah[mi], bh[nj]);
                    mma_bf16(acc[mi][nj], ah[mi], bl[nj]);
                    mma_bf16(acc[mi][nj], al[mi], bh[nj]);
                }
        }
        __syncthreads();
    }

    // epilogue
#pragma unroll
    for (int mi = 0; mi < 4; mi++) {
        int r = m0 + wm + mi * 16 + g;
#pragma unroll
        for (int nj = 0; nj < 4; nj++) {
            int c = n0 + wn + nj * 8 + 2 * q;
            *(float2*)(C + (size_t)r * N + c)       = make_float2(acc[mi][nj][0], acc[mi][nj][1]);
            *(float2*)(C + (size_t)(r + 8) * N + c) = make_float2(acc[mi][nj][2], acc[mi][nj][3]);
        }
    }
}

// ---------------- RoPE (in-place on q or k buffer) ----------------
// position_ids == arange(S) for B=1, so position = s directly.
__global__ void rope_kernel(float* __restrict__ x,
                            int nslots, int rowstride, int total) {
    int idx = blockIdx.x * blockDim.x + threadIdx.x;
    if (idx >= total) return;
    int dh = idx & 31;
    int slot = (idx >> 5) % nslots;
    int s = idx / (nslots << 5);
    float pos = (float)s;
    float invf = expf(-(2.0f * dh / 64.0f) * 9.210340371976184f);
    float ang = pos * invf;
    float c = cosf(ang), sn = sinf(ang);
    float* row = x + (size_t)s * rowstride + slot * 64;
    float x0 = row[dh], x1 = row[dh + 32];
    row[dh]      = x0 * c - x1 * sn;
    row[dh + 32] = x1 * c + x0 * sn;
}

// ---------------- lambda_full ----------------
__global__ void lambda_kernel(const float* lq1, const float* lk1,
                              const float* lq2, const float* lk2) {
    float s1 = 0.f, s2 = 0.f;
    for (int i = threadIdx.x; i < 64; i += 32) {
        s1 += lq1[i] * lk1[i];
        s2 += lq2[i] * lk2[i];
    }
#pragma unroll
    for (int o = 16; o; o >>= 1) {
        s1 += __shfl_xor_sync(0xffffffffu, s1, o);
        s2 += __shfl_xor_sync(0xffffffffu, s2, o);
    }
    if (threadIdx.x == 0) g_lambda = expf(s1) - expf(s2) + LAMBDA_INIT;
}

// ---------------- fused dual flash attention + diff + RMSNorm ----------------
#define ATT_PAD 65
#define ATT_SMEM (5 * 64 * ATT_PAD * 4)

__global__ void __launch_bounds__(256) diff_attn_kernel(const float* __restrict__ subln_w) {
    extern __shared__ float sm[];
    float* sQ1 = sm;
    float* sQ2 = sQ1 + 64 * ATT_PAD;
    float* sK1 = sQ2 + 64 * ATT_PAD;  // reused as sP1
    float* sK2 = sK1 + 64 * ATT_PAD;  // reused as sP2
    float* sV  = sK2 + 64 * ATT_PAD;

    const int qb = blockIdx.x, h = blockIdx.y;
    const int hk = h >> 2;  // NREP = 4
    const int tid = threadIdx.x;
    const int ty = tid >> 4, tx = tid & 15;

    for (int idx = tid * 4; idx < 64 * 64; idx += 1024) {
        int r = idx >> 6, d = idx & 63;
        const float* qrow = g_q + (size_t)(qb * 64 + r) * 4096 + h * 64 + d;
        float4 q1 = *(const float4*)qrow;
        float4 q2 = *(const float4*)(qrow + 2048);
        float* p1 = &sQ1[r * ATT_PAD + d];
        float* p2 = &sQ2[r * ATT_PAD + d];
        p1[0] = q1.x; p1[1] = q1.y; p1[2] = q1.z; p1[3] = q1.w;
        p2[0] = q2.x; p2[1] = q2.y; p2[2] = q2.z; p2[3] = q2.w;
    }

    float O1[4][4] = {}, O2[4][4] = {};
    float m1[4], l1[4], m2[4], l2[4];
#pragma unroll
    for (int i = 0; i < 4; i++) { m1[i] = m2[i] = -1e30f; l1[i] = l2[i] = 0.f; }

    for (int kb = 0; kb <= qb; kb++) {
        __syncthreads();
        for (int idx = tid * 4; idx < 64 * 64; idx += 1024) {
            int c = idx >> 6, d = idx & 63;
            const float* krow = g_k + (size_t)(kb * 64 + c) * 1024 + hk * 64 + d;
            float4 k1 = *(const float4*)krow;
            float4 k2 = *(const float4*)(krow + 512);
            const float* vrow = g_v + (size_t)(kb * 64 + c) * 512 + hk * 64 + d;
            float4 vv = *(const float4*)vrow;
            float* p1 = &sK1[c * ATT_PAD + d];
            float* p2 = &sK2[c * ATT_PAD + d];
            float* pv = &sV[c * ATT_PAD + d];
            p1[0] = k1.x; p1[1] = k1.y; p1[2] = k1.z; p1[3] = k1.w;
            p2[0] = k2.x; p2[1] = k2.y; p2[2] = k2.z; p2[3] = k2.w;
            pv[0] = vv.x; pv[1] = vv.y; pv[2] = vv.z; pv[3] = vv.w;
        }
        __syncthreads();

        float s1[4][4] = {}, s2[4][4] = {};
#pragma unroll 4
        for (int d = 0; d < 64; d++) {
            float a1[4], b1[4], a2[4], b2[4];
#pragma unroll
            for (int i = 0; i < 4; i++) {
                a1[i] = sQ1[(ty + 16 * i) * ATT_PAD + d];
                a2[i] = sQ2[(ty + 16 * i) * ATT_PAD + d];
            }
#pragma unroll
            for (int j = 0; j < 4; j++) {
                b1[j] = sK1[(tx + 16 * j) * ATT_PAD + d];
                b2[j] = sK2[(tx + 16 * j) * ATT_PAD + d];
            }
#pragma unroll
            for (int i = 0; i < 4; i++)
#pragma unroll
                for (int j = 0; j < 4; j++) {
                    s1[i][j] = fmaf(a1[i], b1[j], s1[i][j]);
                    s2[i][j] = fmaf(a2[i], b2[j], s2[i][j]);
                }
        }
        const float scale = 0.125f;
#pragma unroll
        for (int i = 0; i < 4; i++)
#pragma unroll
            for (int j = 0; j < 4; j++) { s1[i][j] *= scale; s2[i][j] *= scale; }
        if (kb == qb) {
#pragma unroll
            for (int i = 0; i < 4; i++) {
                int qg = qb * 64 + ty + 16 * i;
#pragma unroll
                for (int j = 0; j < 4; j++) {
                    int kg = kb * 64 + tx + 16 * j;
                    if (kg > qg) { s1[i][j] = -1e30f; s2[i][j] = -1e30f; }
                }
            }
        }

#pragma unroll
        for (int i = 0; i < 4; i++) {
            float mx = fmaxf(fmaxf(s1[i][0], s1[i][1]), fmaxf(s1[i][2], s1[i][3]));
#pragma unroll
            for (int o = 8; o; o >>= 1) mx = fmaxf(mx, __shfl_xor_sync(0xffffffffu, mx, o, 16));
            float mn = fmaxf(m1[i], mx);
            float corr = expf(m1[i] - mn);
            float rs = 0.f;
#pragma unroll
            for (int j = 0; j < 4; j++) { float p = expf(s1[i][j] - mn); s1[i][j] = p; rs += p; }
#pragma unroll
            for (int o = 8; o; o >>= 1) rs += __shfl_xor_sync(0xffffffffu, rs, o, 16);
            l1[i] = l1[i] * corr + rs;
            m1[i] = mn;
#pragma unroll
            for (int j = 0; j < 4; j++) O1[i][j] *= corr;

            mx = fmaxf(fmaxf(s2[i][0], s2[i][1]), fmaxf(s2[i][2], s2[i][3]));
#pragma unroll
            for (int o = 8; o; o >>= 1) mx = fmaxf(mx, __shfl_xor_sync(0xffffffffu, mx, o, 16));
            mn = fmaxf(m2[i], mx);
            corr = expf(m2[i] - mn);
            rs = 0.f;
#pragma unroll
            for (int j = 0; j < 4; j++) { float p = expf(s2[i][j] - mn); s2[i][j] = p; rs += p; }
#pragma unroll
            for (int o = 8; o; o >>= 1) rs += __shfl_xor_sync(0xffffffffu, rs, o, 16);
            l2[i] = l2[i] * corr + rs;
            m2[i] = mn;
#pragma unroll
            for (int j = 0; j < 4; j++) O2[i][j] *= corr;
        }

        __syncthreads();
#pragma unroll
        for (int i = 0; i < 4; i++)
#pragma unroll
            for (int j = 0; j < 4; j++) {
                sK1[(ty + 16 * i) * ATT_PAD + tx + 16 * j] = s1[i][j];
                sK2[(ty + 16 * i) * ATT_PAD + tx + 16 * j] = s2[i][j];
            }
        __syncthreads();

#pragma unroll 2
        for (int c = 0; c < 64; c++) {
            float v[4];
#pragma unroll
            for (int j = 0; j < 4; j++) v[j] = sV[c * ATT_PAD + tx + 16 * j];
#pragma unroll
            for (int i = 0; i < 4; i++) {
                float p1 = sK1[(ty + 16 * i) * ATT_PAD + c];
                float p2 = sK2[(ty + 16 * i) * ATT_PAD + c];
#pragma unroll
                for (int j = 0; j < 4; j++) {
                    O1[i][j] = fmaf(p1, v[j], O1[i][j]);
                    O2[i][j] = fmaf(p2, v[j], O2[i][j]);
                }
            }
        }
    }

    const float lam = g_lambda;
    float w[4];
#pragma unroll
    for (int j = 0; j < 4; j++) w[j] = subln_w[tx + 16 * j];
#pragma unroll
    for (int i = 0; i < 4; i++) {
        float inv1 = 1.f / l1[i], inv2 = 1.f / l2[i];
        float o[4];
        float ss = 0.f;
#pragma unroll
        for (int j = 0; j < 4; j++) {
            o[j] = O1[i][j] * inv1 - lam * (O2[i][j] * inv2);
            ss += o[j] * o[j];
        }
#pragma unroll
        for (int off = 8; off; off >>= 1) ss += __shfl_xor_sync(0xffffffffu, ss, off, 16);
        float rms = rsqrtf(ss * (1.0f / 64.0f) + 1e-6f);
        float k = rms * (1.0f - LAMBDA_INIT);
        int sg = qb * 64 + ty + 16 * i;
#pragma unroll
        for (int j = 0; j < 4; j++)
            g_att[(size_t)sg * HID_ + h * 64 + tx + 16 * j] = o[j] * k * w[j];
    }
}

// ---------------- launch ----------------
extern "C" void kernel_launch(void* const* d_in, const int* in_sizes, int n_in,
                              void* d_out, int out_size) {
    const float* hs   = (const float*)d_in[0];
    const float* Wq   = (const float*)d_in[1];
    const float* Wk   = (const float*)d_in[2];
    const float* Wv   = (const float*)d_in[3];
    const float* Wo   = (const float*)d_in[4];
    const float* lq1  = (const float*)d_in[5];
    const float* lk1  = (const float*)d_in[6];
    const float* lq2  = (const float*)d_in[7];
    const float* lk2  = (const float*)d_in[8];
    const float* subw = (const float*)d_in[9];
    float* out = (float*)d_out;

    void *pq, *pk, *pv, *pa;
    cudaGetSymbolAddress(&pq, g_q);
    cudaGetSymbolAddress(&pk, g_k);
    cudaGetSymbolAddress(&pv, g_v);
    cudaGetSymbolAddress(&pa, g_att);
    cudaFuncSetAttribute(diff_attn_kernel,
                         cudaFuncAttributeMaxDynamicSharedMemorySize, ATT_SMEM);

    // projections (tensor-core bf16-split GEMM)
    gemm_bf3<<<dim3(4096 / 128, S_LEN / 128), 256>>>(hs, Wq, (float*)pq, S_LEN, 4096, HID_);
    gemm_bf3<<<dim3(1024 / 128, S_LEN / 128), 256>>>(hs, Wk, (float*)pk, S_LEN, 1024, HID_);
    gemm_bf3<<<dim3(512 / 128,  S_LEN / 128), 256>>>(hs, Wv, (float*)pv, S_LEN, 512, HID_);

    // rope: q has 64 head-slots (q1|q2), k has 16 (k1|k2)
    {
        int tq = S_LEN * 64 * 32;
        rope_kernel<<<(tq + 255) / 256, 256>>>((float*)pq, 64, 4096, tq);
        int tk = S_LEN * 16 * 32;
        rope_kernel<<<(tk + 255) / 256, 256>>>((float*)pk, 16, 1024, tk);
    }

    lambda_kernel<<<1, 32>>>(lq1, lk1, lq2, lk2);

    diff_attn_kernel<<<dim3(S_LEN / 64, NH), 256, ATT_SMEM>>>(subw);

    // output projection
    gemm_bf3<<<dim3(HID_ / 128, S_LEN / 128), 256>>>((float*)pa, Wo, out, S_LEN, HID_, HID_);
}

// round 5
// speedup vs baseline: 2.1940x; 1.6366x over previous
#include <cuda_runtime.h>
#include <cuda_bf16.h>
#include <cstdint>
#include <math.h>

typedef unsigned int u32;

#define S_LEN 2048
#define HID_  2048
#define NH    32
#define NKV   8
#define HD    64
#define LAMBDA_INIT 0.7836057665316245f  // 0.8 - 0.6*exp(-0.3*12)

// ---------------- scratch (device globals; no allocation allowed) ----------------
__device__ float g_q[(size_t)S_LEN * 4096];   // [S, 2*HID]  (q1 | q2) fp32
__device__ float g_k[(size_t)S_LEN * 1024];   // [S, 2*D*HKV] fp32
__device__ float g_v[(size_t)S_LEN * 512];    // [S, D*HKV] fp32
__device__ float g_att[(size_t)S_LEN * HID_]; // [S, H*D]  pre-Wo
__device__ u32   g_qp[(size_t)S_LEN * 4096];  // packed hi|lo bf16, pre-scaled by 1/8
__device__ u32   g_kp[(size_t)S_LEN * 1024];  // packed hi|lo bf16
__device__ u32   g_vp[(size_t)S_LEN * 512];   // packed hi|lo bf16
__device__ float g_lambda;

// ================= common helpers =================
__device__ __forceinline__ u32 pack_bf(float x) {
    __nv_bfloat16 h = __float2bfloat16(x);
    float hf = __bfloat162float(h);
    __nv_bfloat16 l = __float2bfloat16(x - hf);
    unsigned short hs = *reinterpret_cast<unsigned short*>(&h);
    unsigned short ls = *reinterpret_cast<unsigned short*>(&l);
    return ((u32)hs << 16) | (u32)ls;
}

// split pair (x,y) into bf16x2 hi and lo words (low half = x)
__device__ __forceinline__ void split2(float x, float y, u32& hi, u32& lo) {
    float hx = __bfloat162float(__float2bfloat16(x));
    float hy = __bfloat162float(__float2bfloat16(y));
    __nv_bfloat162 hp = __floats2bfloat162_rn(hx, hy);       // exact
    __nv_bfloat162 lp = __floats2bfloat162_rn(x - hx, y - hy);
    hi = *reinterpret_cast<u32*>(&hp);
    lo = *reinterpret_cast<u32*>(&lp);
}

__device__ __forceinline__ void mma_bf16(float* c, const u32* a, const u32* b) {
    asm volatile(
        "mma.sync.aligned.m16n8k16.row.col.f32.bf16.bf16.f32 "
        "{%0,%1,%2,%3}, {%4,%5,%6,%7}, {%8,%9}, {%0,%1,%2,%3};"
        : "+f"(c[0]), "+f"(c[1]), "+f"(c[2]), "+f"(c[3])
        : "r"(a[0]), "r"(a[1]), "r"(a[2]), "r"(a[3]), "r"(b[0]), "r"(b[1]));
}

// ================= bf16 split-precision tensor-core GEMM =================
#define GSTR 36

__global__ void __launch_bounds__(256) gemm_bf3(const float* __restrict__ A,
                                               const float* __restrict__ B,
                                               float* __restrict__ C,
                                               int M, int N, int K) {
    __shared__ u32 sA[128 * GSTR];
    __shared__ u32 sB[128 * GSTR];

    const int tid  = threadIdx.x;
    const int lane = tid & 31;
    const int warp = tid >> 5;
    const int wm = (warp >> 2) * 64;
    const int wn = (warp & 3) * 32;
    const int m0 = blockIdx.y * 128;
    const int n0 = blockIdx.x * 128;
    const int q  = lane & 3;
    const int g  = lane >> 2;

    float acc[4][4][4] = {};

    float4 pa[4], pb[4];
    int rowA[4], slA[4];
#pragma unroll
    for (int it = 0; it < 4; it++) {
        int idx = tid + it * 256;
        rowA[it] = idx >> 3; slA[it] = idx & 7;
    }
#pragma unroll
    for (int it = 0; it < 4; it++) {
        pa[it] = *(const float4*)(A + (size_t)(m0 + rowA[it]) * K + slA[it] * 4);
        pb[it] = *(const float4*)(B + (size_t)(n0 + rowA[it]) * K + slA[it] * 4);
    }

    for (int k0 = 0; k0 < K; k0 += 32) {
#pragma unroll
        for (int it = 0; it < 4; it++) {
            uint4 wa, wb;
            wa.x = pack_bf(pa[it].x); wa.y = pack_bf(pa[it].y);
            wa.z = pack_bf(pa[it].z); wa.w = pack_bf(pa[it].w);
            wb.x = pack_bf(pb[it].x); wb.y = pack_bf(pb[it].y);
            wb.z = pack_bf(pb[it].z); wb.w = pack_bf(pb[it].w);
            *(uint4*)&sA[rowA[it] * GSTR + slA[it] * 4] = wa;
            *(uint4*)&sB[rowA[it] * GSTR + slA[it] * 4] = wb;
        }
        __syncthreads();

        if (k0 + 32 < K) {
#pragma unroll
            for (int it = 0; it < 4; it++) {
                pa[it] = *(const float4*)(A + (size_t)(m0 + rowA[it]) * K + k0 + 32 + slA[it] * 4);
                pb[it] = *(const float4*)(B + (size_t)(n0 + rowA[it]) * K + k0 + 32 + slA[it] * 4);
            }
        }

#pragma unroll
        for (int kk = 0; kk < 32; kk += 16) {
            u32 ah[4][4], al[4][4], bh[4][2], bl[4][2];
#pragma unroll
            for (int mi = 0; mi < 4; mi++) {
                int r = wm + mi * 16 + g;
                uint2 w0 = *(uint2*)&sA[r * GSTR + kk + 2 * q];
                uint2 w1 = *(uint2*)&sA[(r + 8) * GSTR + kk + 2 * q];
                uint2 w2 = *(uint2*)&sA[r * GSTR + kk + 8 + 2 * q];
                uint2 w3 = *(uint2*)&sA[(r + 8) * GSTR + kk + 8 + 2 * q];
                ah[mi][0] = __byte_perm(w0.x, w0.y, 0x7632); al[mi][0] = __byte_perm(w0.x, w0.y, 0x5410);
                ah[mi][1] = __byte_perm(w1.x, w1.y, 0x7632); al[mi][1] = __byte_perm(w1.x, w1.y, 0x5410);
                ah[mi][2] = __byte_perm(w2.x, w2.y, 0x7632); al[mi][2] = __byte_perm(w2.x, w2.y, 0x5410);
                ah[mi][3] = __byte_perm(w3.x, w3.y, 0x7632); al[mi][3] = __byte_perm(w3.x, w3.y, 0x5410);
            }
#pragma unroll
            for (int nj = 0; nj < 4; nj++) {
                int n = wn + nj * 8 + g;
                uint2 w0 = *(uint2*)&sB[n * GSTR + kk + 2 * q];
                uint2 w1 = *(uint2*)&sB[n * GSTR + kk + 8 + 2 * q];
                bh[nj][0] = __byte_perm(w0.x, w0.y, 0x7632); bl[nj][0] = __byte_perm(w0.x, w0.y, 0x5410);
                bh[nj][1] = __byte_perm(w1.x, w1.y, 0x7632); bl[nj][1] = __byte_perm(w1.x, w1.y, 0x5410);
            }
#pragma unroll
            for (int mi = 0; mi < 4; mi++)
#pragma unroll
                for (int nj = 0; nj < 4; nj++) {
                    mma_bf16(acc[mi][nj], ah[mi], bh[nj]);
                    mma_bf16(acc[mi][nj], ah[mi], bl[nj]);
                    mma_bf16(acc[mi][nj], al[mi], bh[nj]);
                }
        }
        __syncthreads();
    }

#pragma unroll
    for (int mi = 0; mi < 4; mi++) {
        int r = m0 + wm + mi * 16 + g;
#pragma unroll
        for (int nj = 0; nj < 4; nj++) {
            int c = n0 + wn + nj * 8 + 2 * q;
            *(float2*)(C + (size_t)r * N + c)       = make_float2(acc[mi][nj][0], acc[mi][nj][1]);
            *(float2*)(C + (size_t)(r + 8) * N + c) = make_float2(acc[mi][nj][2], acc[mi][nj][3]);
        }
    }
}

// ---------------- RoPE + pack (fp32 src -> packed u32 dst) ----------------
// position_ids == arange(S) for B=1, so position = s directly.
__global__ void rope_pack_kernel(const float* __restrict__ src, u32* __restrict__ dst,
                                 int nslots, int rowstride, int total, float prescale) {
    int idx = blockIdx.x * blockDim.x + threadIdx.x;
    if (idx >= total) return;
    int dh = idx & 31;
    int slot = (idx >> 5) % nslots;
    int s = idx / (nslots << 5);
    float pos = (float)s;
    float invf = expf(-(2.0f * dh / 64.0f) * 9.210340371976184f);
    float ang = pos * invf;
    float c = cosf(ang), sn = sinf(ang);
    const float* row = src + (size_t)s * rowstride + slot * 64;
    u32* drow = dst + (size_t)s * rowstride + slot * 64;
    float x0 = row[dh], x1 = row[dh + 32];
    float y0 = (x0 * c - x1 * sn) * prescale;
    float y1 = (x1 * c + x0 * sn) * prescale;
    drow[dh]      = pack_bf(y0);
    drow[dh + 32] = pack_bf(y1);
}

// ---------------- pack V ----------------
__global__ void pack_kernel(const float* __restrict__ src, u32* __restrict__ dst, int n) {
    int i = blockIdx.x * blockDim.x + threadIdx.x;
    if (i < n) dst[i] = pack_bf(src[i]);
}

// ---------------- lambda_full ----------------
__global__ void lambda_kernel(const float* lq1, const float* lk1,
                              const float* lq2, const float* lk2) {
    float s1 = 0.f, s2 = 0.f;
    for (int i = threadIdx.x; i < 64; i += 32) {
        s1 += lq1[i] * lk1[i];
        s2 += lq2[i] * lk2[i];
    }
#pragma unroll
    for (int o = 16; o; o >>= 1) {
        s1 += __shfl_xor_sync(0xffffffffu, s1, o);
        s2 += __shfl_xor_sync(0xffffffffu, s2, o);
    }
    if (threadIdx.x == 0) g_lambda = expf(s1) - expf(s2) + LAMBDA_INIT;
}

// ============ fused dual flash attention (tensor core) + diff + RMSNorm ============
// grid (qb=32, h=32), 128 thr = 4 warps; warp w owns q rows 16w..16w+15.
// Scores via mma m16n8k16 bf16-split x3; P@V likewise (both streams share V frags).
#define KSTR 68
#define ATT_SMEM_BYTES (3 * 64 * KSTR * 4)

__device__ __forceinline__ void online_softmax(float (&s)[8][4], float* m, float* l,
                                               float (&O)[8][4]) {
    float mx0 = -1e30f, mx1 = -1e30f;
#pragma unroll
    for (int jn = 0; jn < 8; jn++) {
        mx0 = fmaxf(mx0, fmaxf(s[jn][0], s[jn][1]));
        mx1 = fmaxf(mx1, fmaxf(s[jn][2], s[jn][3]));
    }
    mx0 = fmaxf(mx0, __shfl_xor_sync(0xffffffffu, mx0, 1));
    mx0 = fmaxf(mx0, __shfl_xor_sync(0xffffffffu, mx0, 2));
    mx1 = fmaxf(mx1, __shfl_xor_sync(0xffffffffu, mx1, 1));
    mx1 = fmaxf(mx1, __shfl_xor_sync(0xffffffffu, mx1, 2));
    float mn0 = fmaxf(m[0], mx0), mn1 = fmaxf(m[1], mx1);
    float c0 = __expf(m[0] - mn0), c1 = __expf(m[1] - mn1);
    float rs0 = 0.f, rs1 = 0.f;
#pragma unroll
    for (int jn = 0; jn < 8; jn++) {
        s[jn][0] = __expf(s[jn][0] - mn0);
        s[jn][1] = __expf(s[jn][1] - mn0);
        s[jn][2] = __expf(s[jn][2] - mn1);
        s[jn][3] = __expf(s[jn][3] - mn1);
        rs0 += s[jn][0] + s[jn][1];
        rs1 += s[jn][2] + s[jn][3];
    }
    rs0 += __shfl_xor_sync(0xffffffffu, rs0, 1);
    rs0 += __shfl_xor_sync(0xffffffffu, rs0, 2);
    rs1 += __shfl_xor_sync(0xffffffffu, rs1, 1);
    rs1 += __shfl_xor_sync(0xffffffffu, rs1, 2);
    l[0] = l[0] * c0 + rs0; m[0] = mn0;
    l[1] = l[1] * c1 + rs1; m[1] = mn1;
#pragma unroll
    for (int jn = 0; jn < 8; jn++) {
        O[jn][0] *= c0; O[jn][1] *= c0;
        O[jn][2] *= c1; O[jn][3] *= c1;
    }
}

__global__ void __launch_bounds__(128) diff_attn_mma(const float* __restrict__ subln_w) {
    extern __shared__ u32 smem_u[];
    u32* sK1 = smem_u;
    u32* sK2 = sK1 + 64 * KSTR;
    u32* sV  = sK2 + 64 * KSTR;

    const int qb = blockIdx.x, h = blockIdx.y;
    const int hk = h >> 2;     // NREP = 4
    const int tid = threadIdx.x;
    const int warp = tid >> 5, lane = tid & 31;
    const int g = lane >> 2, q = lane & 3;

    const int r0 = qb * 64 + warp * 16 + g;   // global q rows
    const int r1 = r0 + 8;

    // load Q fragments (packed, pre-scaled by 1/8). a0..a3 per k16-step.
    u32 qh1[4][4], ql1[4][4], qh2[4][4], ql2[4][4];
    {
        const u32* b0 = g_qp + (size_t)r0 * 4096 + h * 64;
        const u32* b1 = g_qp + (size_t)r1 * 4096 + h * 64;
#pragma unroll
        for (int t = 0; t < 4; t++) {
            int kk = 16 * t;
            uint2 w;
            w = *(const uint2*)(b0 + kk + 2 * q);
            qh1[t][0] = __byte_perm(w.x, w.y, 0x7632); ql1[t][0] = __byte_perm(w.x, w.y, 0x5410);
            w = *(const uint2*)(b1 + kk + 2 * q);
            qh1[t][1] = __byte_perm(w.x, w.y, 0x7632); ql1[t][1] = __byte_perm(w.x, w.y, 0x5410);
            w = *(const uint2*)(b0 + kk + 8 + 2 * q);
            qh1[t][2] = __byte_perm(w.x, w.y, 0x7632); ql1[t][2] = __byte_perm(w.x, w.y, 0x5410);
            w = *(const uint2*)(b1 + kk + 8 + 2 * q);
            qh1[t][3] = __byte_perm(w.x, w.y, 0x7632); ql1[t][3] = __byte_perm(w.x, w.y, 0x5410);
            w = *(const uint2*)(b0 + 2048 + kk + 2 * q);
            qh2[t][0] = __byte_perm(w.x, w.y, 0x7632); ql2[t][0] = __byte_perm(w.x, w.y, 0x5410);
            w = *(const uint2*)(b1 + 2048 + kk + 2 * q);
            qh2[t][1] = __byte_perm(w.x, w.y, 0x7632); ql2[t][1] = __byte_perm(w.x, w.y, 0x5410);
            w = *(const uint2*)(b0 + 2048 + kk + 8 + 2 * q);
            qh2[t][2] = __byte_perm(w.x, w.y, 0x7632); ql2[t][2] = __byte_perm(w.x, w.y, 0x5410);
            w = *(const uint2*)(b1 + 2048 + kk + 8 + 2 * q);
            qh2[t][3] = __byte_perm(w.x, w.y, 0x7632); ql2[t][3] = __byte_perm(w.x, w.y, 0x5410);
        }
    }

    float O1[8][4] = {}, O2[8][4] = {};
    float m1[2] = {-1e30f, -1e30f}, l1[2] = {0.f, 0.f};
    float m2[2] = {-1e30f, -1e30f}, l2[2] = {0.f, 0.f};

    for (int kb = 0; kb <= qb; kb++) {
        __syncthreads();
        // stage packed K1/K2/V tiles
        for (int idx = tid; idx < 1024; idx += 128) {
            int row = idx >> 4, d4 = (idx & 15) * 4;
            size_t gr = (size_t)(kb * 64 + row);
            *(uint4*)&sK1[row * KSTR + d4] = *(const uint4*)(g_kp + gr * 1024 + hk * 64 + d4);
            *(uint4*)&sK2[row * KSTR + d4] = *(const uint4*)(g_kp + gr * 1024 + 512 + hk * 64 + d4);
            *(uint4*)&sV [row * KSTR + d4] = *(const uint4*)(g_vp + gr * 512 + hk * 64 + d4);
        }
        __syncthreads();

        // --- scores (both streams) ---
        float s1[8][4] = {}, s2[8][4] = {};
#pragma unroll
        for (int t = 0; t < 4; t++) {
            int kk = 16 * t;
#pragma unroll
            for (int jn = 0; jn < 8; jn++) {
                int n = 8 * jn + g;
                u32 bh[2], bl[2];
                uint2 w0 = *(const uint2*)&sK1[n * KSTR + kk + 2 * q];
                uint2 w1 = *(const uint2*)&sK1[n * KSTR + kk + 8 + 2 * q];
                bh[0] = __byte_perm(w0.x, w0.y, 0x7632); bl[0] = __byte_perm(w0.x, w0.y, 0x5410);
                bh[1] = __byte_perm(w1.x, w1.y, 0x7632); bl[1] = __byte_perm(w1.x, w1.y, 0x5410);
                mma_bf16(s1[jn], qh1[t], bh);
                mma_bf16(s1[jn], qh1[t], bl);
                mma_bf16(s1[jn], ql1[t], bh);
                w0 = *(const uint2*)&sK2[n * KSTR + kk + 2 * q];
                w1 = *(const uint2*)&sK2[n * KSTR + kk + 8 + 2 * q];
                bh[0] = __byte_perm(w0.x, w0.y, 0x7632); bl[0] = __byte_perm(w0.x, w0.y, 0x5410);
                bh[1] = __byte_perm(w1.x, w1.y, 0x7632); bl[1] = __byte_perm(w1.x, w1.y, 0x5410);
                mma_bf16(s2[jn], qh2[t], bh);
                mma_bf16(s2[jn], qh2[t], bl);
                mma_bf16(s2[jn], ql2[t], bh);
            }
        }

        // causal mask (scale already folded into Q)
        if (kb == qb) {
#pragma unroll
            for (int jn = 0; jn < 8; jn++) {
                int c0 = kb * 64 + 8 * jn + 2 * q;
                if (c0 > r0)     { s1[jn][0] = -1e30f; s2[jn][0] = -1e30f; }
                if (c0 + 1 > r0) { s1[jn][1] = -1e30f; s2[jn][1] = -1e30f; }
                if (c0 > r1)     { s1[jn][2] = -1e30f; s2[jn][2] = -1e30f; }
                if (c0 + 1 > r1) { s1[jn][3] = -1e30f; s2[jn][3] = -1e30f; }
            }
        }

        online_softmax(s1, m1, l1, O1);
        online_softmax(s2, m2, l2, O2);

        // --- P @ V (both streams share V fragments) ---
#pragma unroll
        for (int t = 0; t < 4; t++) {
            int kk = 16 * t;
            u32 p1h[4], p1l[4], p2h[4], p2l[4];
            split2(s1[2*t][0],   s1[2*t][1],   p1h[0], p1l[0]);
            split2(s1[2*t][2],   s1[2*t][3],   p1h[1], p1l[1]);
            split2(s1[2*t+1][0], s1[2*t+1][1], p1h[2], p1l[2]);
            split2(s1[2*t+1][2], s1[2*t+1][3], p1h[3], p1l[3]);
            split2(s2[2*t][0],   s2[2*t][1],   p2h[0], p2l[0]);
            split2(s2[2*t][2],   s2[2*t][3],   p2h[1], p2l[1]);
            split2(s2[2*t+1][0], s2[2*t+1][1], p2h[2], p2l[2]);
            split2(s2[2*t+1][2], s2[2*t+1][3], p2h[3], p2l[3]);
#pragma unroll
            for (int jn = 0; jn < 8; jn++) {
                int n = 8 * jn + g;
                u32 w0 = sV[(kk + 2 * q)     * KSTR + n];
                u32 w1 = sV[(kk + 2 * q + 1) * KSTR + n];
                u32 w2 = sV[(kk + 8 + 2 * q)     * KSTR + n];
                u32 w3 = sV[(kk + 8 + 2 * q + 1) * KSTR + n];
                u32 vh[2] = {__byte_perm(w0, w1, 0x7632), __byte_perm(w2, w3, 0x7632)};
                u32 vl[2] = {__byte_perm(w0, w1, 0x5410), __byte_perm(w2, w3, 0x5410)};
                mma_bf16(O1[jn], p1h, vh);
                mma_bf16(O1[jn], p1h, vl);
                mma_bf16(O1[jn], p1l, vh);
                mma_bf16(O2[jn], p2h, vh);
                mma_bf16(O2[jn], p2h, vl);
                mma_bf16(O2[jn], p2l, vh);
            }
        }
    }

    // epilogue: diff, RMSNorm over D, subln scale, (1 - lambda_init)
    const float lam = g_lambda;
    const float il10 = 1.f / l1[0], il11 = 1.f / l1[1];
    const float il20 = 1.f / l2[0], il21 = 1.f / l2[1];
    float oA[8][2], oB[8][2];
    float ss0 = 0.f, ss1 = 0.f;
#pragma unroll
    for (int jn = 0; jn < 8; jn++) {
        float a0 = O1[jn][0] * il10 - lam * (O2[jn][0] * il20);
        float a1 = O1[jn][1] * il10 - lam * (O2[jn][1] * il20);
        float b0 = O1[jn][2] * il11 - lam * (O2[jn][2] * il21);
        float b1 = O1[jn][3] * il11 - lam * (O2[jn][3] * il21);
        oA[jn][0] = a0; oA[jn][1] = a1;
        oB[jn][0] = b0; oB[jn][1] = b1;
        ss0 += a0 * a0 + a1 * a1;
        ss1 += b0 * b0 + b1 * b1;
    }
    ss0 += __shfl_xor_sync(0xffffffffu, ss0, 1);
    ss0 += __shfl_xor_sync(0xffffffffu, ss0, 2);
    ss1 += __shfl_xor_sync(0xffffffffu, ss1, 1);
    ss1 += __shfl_xor_sync(0xffffffffu, ss1, 2);
    float k0 = rsqrtf(ss0 * (1.0f / 64.0f) + 1e-6f) * (1.0f - LAMBDA_INIT);
    float k1 = rsqrtf(ss1 * (1.0f / 64.0f) + 1e-6f) * (1.0f - LAMBDA_INIT);
#pragma unroll
    for (int jn = 0; jn < 8; jn++) {
        int col = 8 * jn + 2 * q;
        float w0 = subln_w[col], w1 = subln_w[col + 1];
        *(float2*)(g_att + (size_t)r0 * HID_ + h * 64 + col) =
            make_float2(oA[jn][0] * k0 * w0, oA[jn][1] * k0 * w1);
        *(float2*)(g_att + (size_t)r1 * HID_ + h * 64 + col) =
            make_float2(oB[jn][0] * k1 * w0, oB[jn][1] * k1 * w1);
    }
}

// ---------------- launch ----------------
extern "C" void kernel_launch(void* const* d_in, const int* in_sizes, int n_in,
                              void* d_out, int out_size) {
    const float* hs   = (const float*)d_in[0];
    const float* Wq   = (const float*)d_in[1];
    const float* Wk   = (const float*)d_in[2];
    const float* Wv   = (const float*)d_in[3];
    const float* Wo   = (const float*)d_in[4];
    const float* lq1  = (const float*)d_in[5];
    const float* lk1  = (const float*)d_in[6];
    const float* lq2  = (const float*)d_in[7];
    const float* lk2  = (const float*)d_in[8];
    const float* subw = (const float*)d_in[9];
    float* out = (float*)d_out;

    void *pq, *pk, *pv, *pa, *pqp, *pkp, *pvp;
    cudaGetSymbolAddress(&pq, g_q);
    cudaGetSymbolAddress(&pk, g_k);
    cudaGetSymbolAddress(&pv, g_v);
    cudaGetSymbolAddress(&pa, g_att);
    cudaGetSymbolAddress(&pqp, g_qp);
    cudaGetSymbolAddress(&pkp, g_kp);
    cudaGetSymbolAddress(&pvp, g_vp);
    cudaFuncSetAttribute(diff_attn_mma,
                         cudaFuncAttributeMaxDynamicSharedMemorySize, ATT_SMEM_BYTES);

    // projections (tensor-core bf16-split GEMM)
    gemm_bf3<<<dim3(4096 / 128, S_LEN / 128), 256>>>(hs, Wq, (float*)pq, S_LEN, 4096, HID_);
    gemm_bf3<<<dim3(1024 / 128, S_LEN / 128), 256>>>(hs, Wk, (float*)pk, S_LEN, 1024, HID_);
    gemm_bf3<<<dim3(512 / 128,  S_LEN / 128), 256>>>(hs, Wv, (float*)pv, S_LEN, 512, HID_);

    // rope + pack: q (scale 1/8 folded), k
    {
        int tq = S_LEN * 64 * 32;
        rope_pack_kernel<<<(tq + 255) / 256, 256>>>((const float*)pq, (u32*)pqp, 64, 4096, tq, 0.125f);
        int tk = S_LEN * 16 * 32;
        rope_pack_kernel<<<(tk + 255) / 256, 256>>>((const float*)pk, (u32*)pkp, 16, 1024, tk, 1.0f);
        int nv = S_LEN * 512;
        pack_kernel<<<(nv + 255) / 256, 256>>>((const float*)pv, (u32*)pvp, nv);
    }

    lambda_kernel<<<1, 32>>>(lq1, lk1, lq2, lk2);

    diff_attn_mma<<<dim3(S_LEN / 64, NH), 128, ATT_SMEM_BYTES>>>(subw);

    // output projection
    gemm_bf3<<<dim3(HID_ / 128, S_LEN / 128), 256>>>((float*)pa, Wo, out, S_LEN, HID_, HID_);
}

// round 6
// speedup vs baseline: 2.4221x; 1.1040x over previous
#include <cuda_runtime.h>
#include <cuda_bf16.h>
#include <cstdint>
#include <math.h>

typedef unsigned int u32;

#define S_LEN 2048
#define HID_  2048
#define NH    32
#define NKV   8
#define HD    64
#define LAMBDA_INIT 0.7836057665316245f  // 0.8 - 0.6*exp(-0.3*12)

// ---------------- scratch (device globals; no allocation allowed) ----------------
__device__ float g_q[(size_t)S_LEN * 4096];   // [S, 2*HID]  (q1 | q2) fp32
__device__ float g_k[(size_t)S_LEN * 1024];   // [S, 2*D*HKV] fp32
__device__ float g_v[(size_t)S_LEN * 512];    // [S, D*HKV] fp32
__device__ u32   g_qp[(size_t)S_LEN * 4096];  // packed hi|lo bf16, pre-scaled 1/8
__device__ u32   g_kp[(size_t)S_LEN * 1024];
__device__ u32   g_vp[(size_t)S_LEN * 512];
__device__ u32   g_attp[(size_t)S_LEN * HID_]; // packed pre-Wo activation
__device__ u32   g_hsp[(size_t)S_LEN * HID_];  // packed hidden_states
__device__ u32   g_wqp[(size_t)4096 * HID_];   // packed weights
__device__ u32   g_wkp[(size_t)1024 * HID_];
__device__ u32   g_wvp[(size_t)512 * HID_];
__device__ u32   g_wop[(size_t)HID_ * HID_];
__device__ float g_lambda;

// ================= common helpers =================
__device__ __forceinline__ u32 pack_bf(float x) {
    __nv_bfloat16 h = __float2bfloat16(x);
    float hf = __bfloat162float(h);
    __nv_bfloat16 l = __float2bfloat16(x - hf);
    unsigned short hs = *reinterpret_cast<unsigned short*>(&h);
    unsigned short ls = *reinterpret_cast<unsigned short*>(&l);
    return ((u32)hs << 16) | (u32)ls;
}

__device__ __forceinline__ void split2(float x, float y, u32& hi, u32& lo) {
    float hx = __bfloat162float(__float2bfloat16(x));
    float hy = __bfloat162float(__float2bfloat16(y));
    __nv_bfloat162 hp = __floats2bfloat162_rn(hx, hy);
    __nv_bfloat162 lp = __floats2bfloat162_rn(x - hx, y - hy);
    hi = *reinterpret_cast<u32*>(&hp);
    lo = *reinterpret_cast<u32*>(&lp);
}

__device__ __forceinline__ void mma_bf16(float* c, const u32* a, const u32* b) {
    asm volatile(
        "mma.sync.aligned.m16n8k16.row.col.f32.bf16.bf16.f32 "
        "{%0,%1,%2,%3}, {%4,%5,%6,%7}, {%8,%9}, {%0,%1,%2,%3};"
        : "+f"(c[0]), "+f"(c[1]), "+f"(c[2]), "+f"(c[3])
        : "r"(a[0]), "r"(a[1]), "r"(a[2]), "r"(a[3]), "r"(b[0]), "r"(b[1]));
}

__device__ __forceinline__ void cp_async16(u32* smem_dst, const u32* gptr) {
    u32 addr = (u32)__cvta_generic_to_shared(smem_dst);
    asm volatile("cp.async.cg.shared.global [%0], [%1], 16;" :: "r"(addr), "l"(gptr));
}

// ======== bf16 split GEMM, pre-packed inputs, cp.async 2-stage pipeline ========
// C[M,N] = A[M,K] @ B[N,K]^T; A,B packed u32 hi|lo. Block 128x128, BK=32.
#define GSTR 36
#define GEMM_STAGE_WORDS (2 * 128 * GSTR)          // A + B per stage
#define GEMM_SMEM_BYTES  (2 * GEMM_STAGE_WORDS * 4) // 2 stages = 73728 B

__global__ void __launch_bounds__(256) gemm_bf3p(const u32* __restrict__ A,
                                                 const u32* __restrict__ B,
                                                 float* __restrict__ C,
                                                 int M, int N, int K) {
    extern __shared__ u32 smem[];

    const int tid  = threadIdx.x;
    const int lane = tid & 31;
    const int warp = tid >> 5;
    const int wm = (warp >> 2) * 64;
    const int wn = (warp & 3) * 32;
    const int m0 = blockIdx.y * 128;
    const int n0 = blockIdx.x * 128;
    const int q  = lane & 3;
    const int g  = lane >> 2;

    int rowL[4], slL[4];
#pragma unroll
    for (int it = 0; it < 4; it++) {
        int idx = tid + it * 256;       // 1024 chunks = 128 rows x 8 uint4-slots
        rowL[it] = idx >> 3; slL[it] = idx & 7;
    }

    float acc[4][4][4] = {};

    // issue stage
    auto issue = [&](int stg, int k0) {
        u32* bA = smem + stg * GEMM_STAGE_WORDS;
        u32* bB = bA + 128 * GSTR;
#pragma unroll
        for (int it = 0; it < 4; it++) {
            cp_async16(&bA[rowL[it] * GSTR + slL[it] * 4],
                       A + (size_t)(m0 + rowL[it]) * K + k0 + slL[it] * 4);
            cp_async16(&bB[rowL[it] * GSTR + slL[it] * 4],
                       B + (size_t)(n0 + rowL[it]) * K + k0 + slL[it] * 4);
        }
        asm volatile("cp.async.commit_group;");
    };

    issue(0, 0);
    const int nk = K >> 5;
    for (int i = 0; i < nk; i++) {
        if (i + 1 < nk) {
            issue((i + 1) & 1, (i + 1) << 5);
            asm volatile("cp.async.wait_group 1;");
        } else {
            asm volatile("cp.async.wait_group 0;");
        }
        __syncthreads();

        const u32* sA = smem + (i & 1) * GEMM_STAGE_WORDS;
        const u32* sB = sA + 128 * GSTR;
#pragma unroll
        for (int kk = 0; kk < 32; kk += 16) {
            u32 ah[4][4], al[4][4], bh[4][2], bl[4][2];
#pragma unroll
            for (int mi = 0; mi < 4; mi++) {
                int r = wm + mi * 16 + g;
                uint2 w0 = *(const uint2*)&sA[r * GSTR + kk + 2 * q];
                uint2 w1 = *(const uint2*)&sA[(r + 8) * GSTR + kk + 2 * q];
                uint2 w2 = *(const uint2*)&sA[r * GSTR + kk + 8 + 2 * q];
                uint2 w3 = *(const uint2*)&sA[(r + 8) * GSTR + kk + 8 + 2 * q];
                ah[mi][0] = __byte_perm(w0.x, w0.y, 0x7632); al[mi][0] = __byte_perm(w0.x, w0.y, 0x5410);
                ah[mi][1] = __byte_perm(w1.x, w1.y, 0x7632); al[mi][1] = __byte_perm(w1.x, w1.y, 0x5410);
                ah[mi][2] = __byte_perm(w2.x, w2.y, 0x7632); al[mi][2] = __byte_perm(w2.x, w2.y, 0x5410);
                ah[mi][3] = __byte_perm(w3.x, w3.y, 0x7632); al[mi][3] = __byte_perm(w3.x, w3.y, 0x5410);
            }
#pragma unroll
            for (int nj = 0; nj < 4; nj++) {
                int n = wn + nj * 8 + g;
                uint2 w0 = *(const uint2*)&sB[n * GSTR + kk + 2 * q];
                uint2 w1 = *(const uint2*)&sB[n * GSTR + kk + 8 + 2 * q];
                bh[nj][0] = __byte_perm(w0.x, w0.y, 0x7632); bl[nj][0] = __byte_perm(w0.x, w0.y, 0x5410);
                bh[nj][1] = __byte_perm(w1.x, w1.y, 0x7632); bl[nj][1] = __byte_perm(w1.x, w1.y, 0x5410);
            }
#pragma unroll
            for (int mi = 0; mi < 4; mi++)
#pragma unroll
                for (int nj = 0; nj < 4; nj++) {
                    mma_bf16(acc[mi][nj], ah[mi], bh[nj]);
                    mma_bf16(acc[mi][nj], ah[mi], bl[nj]);
                    mma_bf16(acc[mi][nj], al[mi], bh[nj]);
                }
        }
        __syncthreads();
    }

#pragma unroll
    for (int mi = 0; mi < 4; mi++) {
        int r = m0 + wm + mi * 16 + g;
#pragma unroll
        for (int nj = 0; nj < 4; nj++) {
            int c = n0 + wn + nj * 8 + 2 * q;
            *(float2*)(C + (size_t)r * N + c)       = make_float2(acc[mi][nj][0], acc[mi][nj][1]);
            *(float2*)(C + (size_t)(r + 8) * N + c) = make_float2(acc[mi][nj][2], acc[mi][nj][3]);
        }
    }
}

// ---------------- pack fp32 -> u32 hi|lo ----------------
__global__ void pack_kernel(const float* __restrict__ src, u32* __restrict__ dst, int n) {
    int i = blockIdx.x * blockDim.x + threadIdx.x;
    if (i < n) dst[i] = pack_bf(src[i]);
}

// ---------------- RoPE + pack ----------------
__global__ void rope_pack_kernel(const float* __restrict__ src, u32* __restrict__ dst,
                                 int nslots, int rowstride, int total, float prescale) {
    int idx = blockIdx.x * blockDim.x + threadIdx.x;
    if (idx >= total) return;
    int dh = idx & 31;
    int slot = (idx >> 5) % nslots;
    int s = idx / (nslots << 5);
    float pos = (float)s;
    float invf = expf(-(2.0f * dh / 64.0f) * 9.210340371976184f);
    float ang = pos * invf;
    float c = cosf(ang), sn = sinf(ang);
    const float* row = src + (size_t)s * rowstride + slot * 64;
    u32* drow = dst + (size_t)s * rowstride + slot * 64;
    float x0 = row[dh], x1 = row[dh + 32];
    float y0 = (x0 * c - x1 * sn) * prescale;
    float y1 = (x1 * c + x0 * sn) * prescale;
    drow[dh]      = pack_bf(y0);
    drow[dh + 32] = pack_bf(y1);
}

// ---------------- lambda_full ----------------
__global__ void lambda_kernel(const float* lq1, const float* lk1,
                              const float* lq2, const float* lk2) {
    float s1 = 0.f, s2 = 0.f;
    for (int i = threadIdx.x; i < 64; i += 32) {
        s1 += lq1[i] * lk1[i];
        s2 += lq2[i] * lk2[i];
    }
#pragma unroll
    for (int o = 16; o; o >>= 1) {
        s1 += __shfl_xor_sync(0xffffffffu, s1, o);
        s2 += __shfl_xor_sync(0xffffffffu, s2, o);
    }
    if (threadIdx.x == 0) g_lambda = expf(s1) - expf(s2) + LAMBDA_INIT;
}

// ============ fused dual flash attention (tensor core) + diff + RMSNorm ============
#define KSTR 68
#define ATT_SMEM_BYTES (3 * 64 * KSTR * 4)

__device__ __forceinline__ void online_softmax(float (&s)[8][4], float* m, float* l,
                                               float (&O)[8][4]) {
    float mx0 = -1e30f, mx1 = -1e30f;
#pragma unroll
    for (int jn = 0; jn < 8; jn++) {
        mx0 = fmaxf(mx0, fmaxf(s[jn][0], s[jn][1]));
        mx1 = fmaxf(mx1, fmaxf(s[jn][2], s[jn][3]));
    }
    mx0 = fmaxf(mx0, __shfl_xor_sync(0xffffffffu, mx0, 1));
    mx0 = fmaxf(mx0, __shfl_xor_sync(0xffffffffu, mx0, 2));
    mx1 = fmaxf(mx1, __shfl_xor_sync(0xffffffffu, mx1, 1));
    mx1 = fmaxf(mx1, __shfl_xor_sync(0xffffffffu, mx1, 2));
    float mn0 = fmaxf(m[0], mx0), mn1 = fmaxf(m[1], mx1);
    float c0 = __expf(m[0] - mn0), c1 = __expf(m[1] - mn1);
    float rs0 = 0.f, rs1 = 0.f;
#pragma unroll
    for (int jn = 0; jn < 8; jn++) {
        s[jn][0] = __expf(s[jn][0] - mn0);
        s[jn][1] = __expf(s[jn][1] - mn0);
        s[jn][2] = __expf(s[jn][2] - mn1);
        s[jn][3] = __expf(s[jn][3] - mn1);
        rs0 += s[jn][0] + s[jn][1];
        rs1 += s[jn][2] + s[jn][3];
    }
    rs0 += __shfl_xor_sync(0xffffffffu, rs0, 1);
    rs0 += __shfl_xor_sync(0xffffffffu, rs0, 2);
    rs1 += __shfl_xor_sync(0xffffffffu, rs1, 1);
    rs1 += __shfl_xor_sync(0xffffffffu, rs1, 2);
    l[0] = l[0] * c0 + rs0; m[0] = mn0;
    l[1] = l[1] * c1 + rs1; m[1] = mn1;
#pragma unroll
    for (int jn = 0; jn < 8; jn++) {
        O[jn][0] *= c0; O[jn][1] *= c0;
        O[jn][2] *= c1; O[jn][3] *= c1;
    }
}

__global__ void __launch_bounds__(128) diff_attn_mma(const float* __restrict__ subln_w) {
    extern __shared__ u32 smem_u[];
    u32* sK1 = smem_u;
    u32* sK2 = sK1 + 64 * KSTR;
    u32* sV  = sK2 + 64 * KSTR;

    const int qb = blockIdx.x, h = blockIdx.y;
    const int hk = h >> 2;
    const int tid = threadIdx.x;
    const int warp = tid >> 5, lane = tid & 31;
    const int g = lane >> 2, q = lane & 3;

    const int r0 = qb * 64 + warp * 16 + g;
    const int r1 = r0 + 8;

    u32 qh1[4][4], ql1[4][4], qh2[4][4], ql2[4][4];
    {
        const u32* b0 = g_qp + (size_t)r0 * 4096 + h * 64;
        const u32* b1 = g_qp + (size_t)r1 * 4096 + h * 64;
#pragma unroll
        for (int t = 0; t < 4; t++) {
            int kk = 16 * t;
            uint2 w;
            w = *(const uint2*)(b0 + kk + 2 * q);
            qh1[t][0] = __byte_perm(w.x, w.y, 0x7632); ql1[t][0] = __byte_perm(w.x, w.y, 0x5410);
            w = *(const uint2*)(b1 + kk + 2 * q);
            qh1[t][1] = __byte_perm(w.x, w.y, 0x7632); ql1[t][1] = __byte_perm(w.x, w.y, 0x5410);
            w = *(const uint2*)(b0 + kk + 8 + 2 * q);
            qh1[t][2] = __byte_perm(w.x, w.y, 0x7632); ql1[t][2] = __byte_perm(w.x, w.y, 0x5410);
            w = *(const uint2*)(b1 + kk + 8 + 2 * q);
            qh1[t][3] = __byte_perm(w.x, w.y, 0x7632); ql1[t][3] = __byte_perm(w.x, w.y, 0x5410);
            w = *(const uint2*)(b0 + 2048 + kk + 2 * q);
            qh2[t][0] = __byte_perm(w.x, w.y, 0x7632); ql2[t][0] = __byte_perm(w.x, w.y, 0x5410);
            w = *(const uint2*)(b1 + 2048 + kk + 2 * q);
            qh2[t][1] = __byte_perm(w.x, w.y, 0x7632); ql2[t][1] = __byte_perm(w.x, w.y, 0x5410);
            w = *(const uint2*)(b0 + 2048 + kk + 8 + 2 * q);
            qh2[t][2] = __byte_perm(w.x, w.y, 0x7632); ql2[t][2] = __byte_perm(w.x, w.y, 0x5410);
            w = *(const uint2*)(b1 + 2048 + kk + 8 + 2 * q);
            qh2[t][3] = __byte_perm(w.x, w.y, 0x7632); ql2[t][3] = __byte_perm(w.x, w.y, 0x5410);
        }
    }

    float O1[8][4] = {}, O2[8][4] = {};
    float m1[2] = {-1e30f, -1e30f}, l1[2] = {0.f, 0.f};
    float m2[2] = {-1e30f, -1e30f}, l2[2] = {0.f, 0.f};

    for (int kb = 0; kb <= qb; kb++) {
        __syncthreads();
        for (int idx = tid; idx < 1024; idx += 128) {
            int row = idx >> 4, d4 = (idx & 15) * 4;
            size_t gr = (size_t)(kb * 64 + row);
            *(uint4*)&sK1[row * KSTR + d4] = *(const uint4*)(g_kp + gr * 1024 + hk * 64 + d4);
            *(uint4*)&sK2[row * KSTR + d4] = *(const uint4*)(g_kp + gr * 1024 + 512 + hk * 64 + d4);
            *(uint4*)&sV [row * KSTR + d4] = *(const uint4*)(g_vp + gr * 512 + hk * 64 + d4);
        }
        __syncthreads();

        float s1[8][4] = {}, s2[8][4] = {};
#pragma unroll
        for (int t = 0; t < 4; t++) {
            int kk = 16 * t;
#pragma unroll
            for (int jn = 0; jn < 8; jn++) {
                int n = 8 * jn + g;
                u32 bh[2], bl[2];
                uint2 w0 = *(const uint2*)&sK1[n * KSTR + kk + 2 * q];
                uint2 w1 = *(const uint2*)&sK1[n * KSTR + kk + 8 + 2 * q];
                bh[0] = __byte_perm(w0.x, w0.y, 0x7632); bl[0] = __byte_perm(w0.x, w0.y, 0x5410);
                bh[1] = __byte_perm(w1.x, w1.y, 0x7632); bl[1] = __byte_perm(w1.x, w1.y, 0x5410);
                mma_bf16(s1[jn], qh1[t], bh);
                mma_bf16(s1[jn], qh1[t], bl);
                mma_bf16(s1[jn], ql1[t], bh);
                w0 = *(const uint2*)&sK2[n * KSTR + kk + 2 * q];
                w1 = *(const uint2*)&sK2[n * KSTR + kk + 8 + 2 * q];
                bh[0] = __byte_perm(w0.x, w0.y, 0x7632); bl[0] = __byte_perm(w0.x, w0.y, 0x5410);
                bh[1] = __byte_perm(w1.x, w1.y, 0x7632); bl[1] = __byte_perm(w1.x, w1.y, 0x5410);
                mma_bf16(s2[jn], qh2[t], bh);
                mma_bf16(s2[jn], qh2[t], bl);
                mma_bf16(s2[jn], ql2[t], bh);
            }
        }

        if (kb == qb) {
#pragma unroll
            for (int jn = 0; jn < 8; jn++) {
                int c0 = kb * 64 + 8 * jn + 2 * q;
                if (c0 > r0)     { s1[jn][0] = -1e30f; s2[jn][0] = -1e30f; }
                if (c0 + 1 > r0) { s1[jn][1] = -1e30f; s2[jn][1] = -1e30f; }
                if (c0 > r1)     { s1[jn][2] = -1e30f; s2[jn][2] = -1e30f; }
                if (c0 + 1 > r1) { s1[jn][3] = -1e30f; s2[jn][3] = -1e30f; }
            }
        }

        online_softmax(s1, m1, l1, O1);
        online_softmax(s2, m2, l2, O2);

#pragma unroll
        for (int t = 0; t < 4; t++) {
            int kk = 16 * t;
            u32 p1h[4], p1l[4], p2h[4], p2l[4];
            split2(s1[2*t][0],   s1[2*t][1],   p1h[0], p1l[0]);
            split2(s1[2*t][2],   s1[2*t][3],   p1h[1], p1l[1]);
            split2(s1[2*t+1][0], s1[2*t+1][1], p1h[2], p1l[2]);
            split2(s1[2*t+1][2], s1[2*t+1][3], p1h[3], p1l[3]);
            split2(s2[2*t][0],   s2[2*t][1],   p2h[0], p2l[0]);
            split2(s2[2*t][2],   s2[2*t][3],   p2h[1], p2l[1]);
            split2(s2[2*t+1][0], s2[2*t+1][1], p2h[2], p2l[2]);
            split2(s2[2*t+1][2], s2[2*t+1][3], p2h[3], p2l[3]);
#pragma unroll
            for (int jn = 0; jn < 8; jn++) {
                int n = 8 * jn + g;
                u32 w0 = sV[(kk + 2 * q)     * KSTR + n];
                u32 w1 = sV[(kk + 2 * q + 1) * KSTR + n];
                u32 w2 = sV[(kk + 8 + 2 * q)     * KSTR + n];
                u32 w3 = sV[(kk + 8 + 2 * q + 1) * KSTR + n];
                u32 vh[2] = {__byte_perm(w0, w1, 0x7632), __byte_perm(w2, w3, 0x7632)};
                u32 vl[2] = {__byte_perm(w0, w1, 0x5410), __byte_perm(w2, w3, 0x5410)};
                mma_bf16(O1[jn], p1h, vh);
                mma_bf16(O1[jn], p1h, vl);
                mma_bf16(O1[jn], p1l, vh);
                mma_bf16(O2[jn], p2h, vh);
                mma_bf16(O2[jn], p2h, vl);
                mma_bf16(O2[jn], p2l, vh);
            }
        }
    }

    // epilogue: diff, RMSNorm, subln, (1-lambda_init); write PACKED for Wo gemm
    const float lam = g_lambda;
    const float il10 = 1.f / l1[0], il11 = 1.f / l1[1];
    const float il20 = 1.f / l2[0], il21 = 1.f / l2[1];
    float oA[8][2], oB[8][2];
    float ss0 = 0.f, ss1 = 0.f;
#pragma unroll
    for (int jn = 0; jn < 8; jn++) {
        float a0 = O1[jn][0] * il10 - lam * (O2[jn][0] * il20);
        float a1 = O1[jn][1] * il10 - lam * (O2[jn][1] * il20);
        float b0 = O1[jn][2] * il11 - lam * (O2[jn][2] * il21);
        float b1 = O1[jn][3] * il11 - lam * (O2[jn][3] * il21);
        oA[jn][0] = a0; oA[jn][1] = a1;
        oB[jn][0] = b0; oB[jn][1] = b1;
        ss0 += a0 * a0 + a1 * a1;
        ss1 += b0 * b0 + b1 * b1;
    }
    ss0 += __shfl_xor_sync(0xffffffffu, ss0, 1);
    ss0 += __shfl_xor_sync(0xffffffffu, ss0, 2);
    ss1 += __shfl_xor_sync(0xffffffffu, ss1, 1);
    ss1 += __shfl_xor_sync(0xffffffffu, ss1, 2);
    float k0 = rsqrtf(ss0 * (1.0f / 64.0f) + 1e-6f) * (1.0f - LAMBDA_INIT);
    float k1 = rsqrtf(ss1 * (1.0f / 64.0f) + 1e-6f) * (1.0f - LAMBDA_INIT);
#pragma unroll
    for (int jn = 0; jn < 8; jn++) {
        int col = 8 * jn + 2 * q;
        float w0 = subln_w[col], w1 = subln_w[col + 1];
        uint2 pA = make_uint2(pack_bf(oA[jn][0] * k0 * w0), pack_bf(oA[jn][1] * k0 * w1));
        uint2 pB = make_uint2(pack_bf(oB[jn][0] * k1 * w0), pack_bf(oB[jn][1] * k1 * w1));
        *(uint2*)(g_attp + (size_t)r0 * HID_ + h * 64 + col) = pA;
        *(uint2*)(g_attp + (size_t)r1 * HID_ + h * 64 + col) = pB;
    }
}

// ---------------- launch ----------------
extern "C" void kernel_launch(void* const* d_in, const int* in_sizes, int n_in,
                              void* d_out, int out_size) {
    const float* hs   = (const float*)d_in[0];
    const float* Wq   = (const float*)d_in[1];
    const float* Wk   = (const float*)d_in[2];
    const float* Wv   = (const float*)d_in[3];
    const float* Wo   = (const float*)d_in[4];
    const float* lq1  = (const float*)d_in[5];
    const float* lk1  = (const float*)d_in[6];
    const float* lq2  = (const float*)d_in[7];
    const float* lk2  = (const float*)d_in[8];
    const float* subw = (const float*)d_in[9];
    float* out = (float*)d_out;

    void *pq, *pk, *pv, *pqp, *pkp, *pvp, *pattp;
    void *phsp, *pwqp, *pwkp, *pwvp, *pwop;
    cudaGetSymbolAddress(&pq, g_q);
    cudaGetSymbolAddress(&pk, g_k);
    cudaGetSymbolAddress(&pv, g_v);
    cudaGetSymbolAddress(&pqp, g_qp);
    cudaGetSymbolAddress(&pkp, g_kp);
    cudaGetSymbolAddress(&pvp, g_vp);
    cudaGetSymbolAddress(&pattp, g_attp);
    cudaGetSymbolAddress(&phsp, g_hsp);
    cudaGetSymbolAddress(&pwqp, g_wqp);
    cudaGetSymbolAddress(&pwkp, g_wkp);
    cudaGetSymbolAddress(&pwvp, g_wvp);
    cudaGetSymbolAddress(&pwop, g_wop);
    cudaFuncSetAttribute(diff_attn_mma,
                         cudaFuncAttributeMaxDynamicSharedMemorySize, ATT_SMEM_BYTES);
    cudaFuncSetAttribute(gemm_bf3p,
                         cudaFuncAttributeMaxDynamicSharedMemorySize, GEMM_SMEM_BYTES);

    // pre-pack activations and weights
    pack_kernel<<<(S_LEN * HID_ + 255) / 256, 256>>>(hs, (u32*)phsp, S_LEN * HID_);
    pack_kernel<<<(4096 * HID_ + 255) / 256, 256>>>(Wq, (u32*)pwqp, 4096 * HID_);
    pack_kernel<<<(1024 * HID_ + 255) / 256, 256>>>(Wk, (u32*)pwkp, 1024 * HID_);
    pack_kernel<<<(512 * HID_ + 255) / 256, 256>>>(Wv, (u32*)pwvp, 512 * HID_);
    pack_kernel<<<(HID_ * HID_ + 255) / 256, 256>>>(Wo, (u32*)pwop, HID_ * HID_);

    // projections (packed-input tensor-core GEMM)
    gemm_bf3p<<<dim3(4096 / 128, S_LEN / 128), 256, GEMM_SMEM_BYTES>>>(
        (const u32*)phsp, (const u32*)pwqp, (float*)pq, S_LEN, 4096, HID_);
    gemm_bf3p<<<dim3(1024 / 128, S_LEN / 128), 256, GEMM_SMEM_BYTES>>>(
        (const u32*)phsp, (const u32*)pwkp, (float*)pk, S_LEN, 1024, HID_);
    gemm_bf3p<<<dim3(512 / 128, S_LEN / 128), 256, GEMM_SMEM_BYTES>>>(
        (const u32*)phsp, (const u32*)pwvp, (float*)pv, S_LEN, 512, HID_);

    // rope + pack q (scale 1/8 folded), k; pack v
    {
        int tq = S_LEN * 64 * 32;
        rope_pack_kernel<<<(tq + 255) / 256, 256>>>((const float*)pq, (u32*)pqp, 64, 4096, tq, 0.125f);
        int tk = S_LEN * 16 * 32;
        rope_pack_kernel<<<(tk + 255) / 256, 256>>>((const float*)pk, (u32*)pkp, 16, 1024, tk, 1.0f);
        int nv = S_LEN * 512;
        pack_kernel<<<(nv + 255) / 256, 256>>>((const float*)pv, (u32*)pvp, nv);
    }

    lambda_kernel<<<1, 32>>>(lq1, lk1, lq2, lk2);

    diff_attn_mma<<<dim3(S_LEN / 64, NH), 128, ATT_SMEM_BYTES>>>(subw);

    // output projection (activation already packed by attention epilogue)
    gemm_bf3p<<<dim3(HID_ / 128, S_LEN / 128), 256, GEMM_SMEM_BYTES>>>(
        (const u32*)pattp, (const u32*)pwop, out, S_LEN, HID_, HID_);
}